// round 10
// baseline (speedup 1.0000x reference)
#include <cuda_runtime.h>
#include <cuda_bf16.h>
#include <math.h>
#include <stdint.h>

// ---------------- problem constants ----------------
#define BSZ   256
#define H1S   12
#define P1    144
#define RTS   512
#define NCP   10
#define K1P   128
#define K2    20736
#define M1    (BSZ*P1)    // 36864
#define M2    4096
#define RECS  102400
#define DEC1  512
#define DEC2  1024
#define ZSPL  8
#define USLICE (M2 * 256)

// ---------------- scratch ----------------
__device__ __nv_bfloat16 g_A1h[M1 * K1P];
__device__ __nv_bfloat16 g_W1h[256 * K1P];
__device__ __nv_bfloat16 g_C1h[M1 * 256];
__device__ __nv_bfloat16 g_W2h[256 * K2];
__device__ float         g_Up[ZSPL * USLICE];   // split-K partials; reused for agreement
__device__ __nv_bfloat16 g_H1h[BSZ * DEC1];
__device__ __nv_bfloat16 g_H2h[BSZ * DEC2];
__device__ float g_X [BSZ * RTS * 8];
__device__ __nv_bfloat16 g_UH[(size_t)BSZ * RTS * 160];
__device__ float g_BIJ[RTS * NCP];
__device__ float g_CIJ[RTS * NCP];
__device__ float g_V [BSZ * 160];
__device__ int   g_IDX[BSZ];

// ---------------- helpers ----------------
__device__ __forceinline__ uint32_t smem_u32(const void* p) {
    uint32_t a;
    asm("{ .reg .u64 t; cvta.to.shared.u64 t, %1; cvt.u32.u64 %0, t; }" : "=r"(a) : "l"(p));
    return a;
}
__device__ __forceinline__ void ldsm_x4(uint32_t addr, uint32_t* r) {
    asm volatile("ldmatrix.sync.aligned.m8n8.x4.shared.b16 {%0,%1,%2,%3}, [%4];"
        : "=r"(r[0]), "=r"(r[1]), "=r"(r[2]), "=r"(r[3]) : "r"(addr));
}
__device__ __forceinline__ void mma_bf16(float* c, const uint32_t* a, const uint32_t* b) {
    asm volatile(
        "mma.sync.aligned.m16n8k16.row.col.f32.bf16.bf16.f32 "
        "{%0,%1,%2,%3}, {%4,%5,%6,%7}, {%8,%9}, {%0,%1,%2,%3};"
        : "+f"(c[0]), "+f"(c[1]), "+f"(c[2]), "+f"(c[3])
        : "r"(a[0]), "r"(a[1]), "r"(a[2]), "r"(a[3]), "r"(b[0]), "r"(b[1]));
}
__device__ __forceinline__ uint4 pack8bf16(float4 f0, float4 f1) {
    __nv_bfloat162 p0 = __halves2bfloat162(__float2bfloat16(f0.x), __float2bfloat16(f0.y));
    __nv_bfloat162 p1 = __halves2bfloat162(__float2bfloat16(f0.z), __float2bfloat16(f0.w));
    __nv_bfloat162 p2 = __halves2bfloat162(__float2bfloat16(f1.x), __float2bfloat16(f1.y));
    __nv_bfloat162 p3 = __halves2bfloat162(__float2bfloat16(f1.z), __float2bfloat16(f1.w));
    uint4 r;
    r.x = *reinterpret_cast<uint32_t*>(&p0);
    r.y = *reinterpret_cast<uint32_t*>(&p1);
    r.z = *reinterpret_cast<uint32_t*>(&p2);
    r.w = *reinterpret_cast<uint32_t*>(&p3);
    return r;
}
__device__ __forceinline__ void cp16(uint32_t d, const void* s) {
    asm volatile("cp.async.cg.shared.global [%0], [%1], 16;" :: "r"(d), "l"(s));
}
__device__ __forceinline__ void cp_commit() { asm volatile("cp.async.commit_group;"); }
template<int NW> __device__ __forceinline__ void cp_wait() {
    asm volatile("cp.async.wait_group %0;" :: "n"(NW));
}

// ============ async HMMA bf16 NT GEMM, BM=128 BN=128 BK=32, 512 thr (16 warps 4x4) ============
template<int MODE, int ACT, int OUT, int SPLITK>
__global__ __launch_bounds__(512)
void hmma_gemm_async(const __nv_bfloat16* __restrict__ Ah,
                     const __nv_bfloat16* __restrict__ Wh,
                     const float* __restrict__ bias,
                     float* __restrict__ Cf,
                     __nv_bfloat16* __restrict__ Coh,
                     int N, int K)
{
    extern __shared__ char sm[];
    constexpr int AP   = 80;
    constexpr int ABYT = 128 * AP;
    constexpr int STG  = 2 * ABYT;   // 20480

    const int t = threadIdx.x;
    const int m0 = blockIdx.x * 128;
    const int n0 = blockIdx.y * 128;
    const uint32_t sbase = smem_u32(sm);

    const int r4 = t >> 2, s4 = t & 3;
    int mbase = 0;
    if (MODE == 1) {
        int m = m0 + r4; int b = m >> 4, p = m & 15;
        mbase = b * 144 + (p >> 2) * 12 + (p & 3);
    }

    const int w = t >> 5, lane = t & 31;
    const int wm = w >> 2, wn = w & 3;          // 4 x 4 warps, 32x32 tile
    const int lrow = (lane & 7) + ((lane >> 3) & 1) * 8;
    const int lk   = ((lane >> 4) & 1) * 8;

    float acc[2][4][4];
#pragma unroll
    for (int mt = 0; mt < 2; mt++)
#pragma unroll
        for (int nt = 0; nt < 4; nt++)
#pragma unroll
            for (int q = 0; q < 4; q++) acc[mt][nt][q] = 0.f;

    auto issue = [&](int s, int k0) {
        uint32_t sb = sbase + (s % 3) * STG;
        size_t aoff;
        if (MODE == 0) {
            aoff = (size_t)(m0 + r4) * K + k0 + s4 * 8;
        } else {
            int rr = k0 >> 8;
            int rowg = mbase + (rr / 9) * 12 + (rr % 9);
            aoff = (size_t)rowg * 256 + (k0 & 255) + s4 * 8;
        }
        cp16(sb + r4 * AP + s4 * 16, Ah + aoff);
        cp16(sb + ABYT + r4 * AP + s4 * 16,
             Wh + (size_t)(n0 + r4) * K + k0 + s4 * 8);
    };
    auto compute = [&](int buf) {
        uint32_t base = sbase + buf * STG;
#pragma unroll
        for (int kk = 0; kk < 32; kk += 16) {
            uint32_t a_h[2][4], b_h[2][4];
#pragma unroll
            for (int mt = 0; mt < 2; mt++) {
                uint32_t ad = base + (wm * 32 + mt * 16 + lrow) * AP + (kk + lk) * 2;
                ldsm_x4(ad, a_h[mt]);
            }
#pragma unroll
            for (int np = 0; np < 2; np++) {
                uint32_t bd = base + ABYT + (wn * 32 + np * 16 + lrow) * AP + (kk + lk) * 2;
                ldsm_x4(bd, b_h[np]);
            }
#pragma unroll
            for (int mt = 0; mt < 2; mt++)
#pragma unroll
                for (int nt = 0; nt < 4; nt++)
                    mma_bf16(acc[mt][nt], a_h[mt], &b_h[nt >> 1][(nt & 1) * 2]);
        }
    };

    const int S = SPLITK ? (K / 32 / ZSPL) : (K / 32);
    const int kbase = SPLITK ? blockIdx.z * (K / ZSPL) : 0;
    issue(0, kbase); cp_commit();
    issue(1, kbase + 32); cp_commit();
    for (int s = 0; s < S; s++) {
        cp_wait<1>();
        __syncthreads();
        if (s + 2 < S) issue(s + 2, kbase + (s + 2) * 32);
        cp_commit();
        compute(s % 3);
    }

    // ---- epilogue ----
    const size_t zoff = SPLITK ? (size_t)blockIdx.z * (size_t)(gridDim.x * 128) * N : 0;
#pragma unroll
    for (int mt = 0; mt < 2; mt++) {
#pragma unroll
        for (int nt = 0; nt < 4; nt++) {
            int row0 = m0 + wm * 32 + mt * 16 + (lane >> 2);
            int col  = n0 + wn * 32 + nt * 8 + (lane & 3) * 2;
            float b0, b1;
            if (SPLITK && blockIdx.z != 0) { b0 = 0.f; b1 = 0.f; }
            else { b0 = bias[col]; b1 = bias[col + 1]; }
#pragma unroll
            for (int half = 0; half < 2; half++) {
                int row = row0 + half * 8;
                float v0 = acc[mt][nt][half * 2 + 0] + b0;
                float v1 = acc[mt][nt][half * 2 + 1] + b1;
                if (ACT == 1) { v0 = fmaxf(v0, 0.f); v1 = fmaxf(v1, 0.f); }
                if (OUT == 0) {
                    *reinterpret_cast<float2*>(&Cf[zoff + (size_t)row * N + col]) = make_float2(v0, v1);
                } else {
                    *reinterpret_cast<__nv_bfloat162*>(&Coh[(size_t)row * N + col]) =
                        __halves2bfloat162(__float2bfloat16(v0), __float2bfloat16(v1));
                }
            }
        }
    }
}

// ============ 2-stage HMMA GEMM, fp32 W converted in loader, 512 thr ============
template<int ACT, int OUT>
__global__ __launch_bounds__(512)
void hmma_gemm_wf(const __nv_bfloat16* __restrict__ Ah,
                  const float* __restrict__ Wf,
                  const float* __restrict__ bias,
                  float* __restrict__ Cf,
                  __nv_bfloat16* __restrict__ Coh,
                  int N, int K)
{
    extern __shared__ char sm[];
    constexpr int AP   = 80;
    constexpr int ABYT = 128 * AP;
    constexpr int STG  = 2 * ABYT;

    const int t = threadIdx.x;
    const int m0 = blockIdx.x * 128;
    const int n0 = blockIdx.y * 128;
    const uint32_t sbase = smem_u32(sm);

    const int r4 = t >> 2, s4 = t & 3;
    const int w = t >> 5, lane = t & 31;
    const int wm = w >> 2, wn = w & 3;
    const int lrow = (lane & 7) + ((lane >> 3) & 1) * 8;
    const int lk   = ((lane >> 4) & 1) * 8;

    float acc[2][4][4];
#pragma unroll
    for (int mt = 0; mt < 2; mt++)
#pragma unroll
        for (int nt = 0; nt < 4; nt++)
#pragma unroll
            for (int q = 0; q < 4; q++) acc[mt][nt][q] = 0.f;

    uint4 rA, rB;
    auto ldg_stage = [&](int k0) {
        rA = *(const uint4*)(Ah + (size_t)(m0 + r4) * K + k0 + s4 * 8);
        const float* wp = Wf + (size_t)(n0 + r4) * K + k0 + s4 * 8;
        rB = pack8bf16(*(const float4*)wp, *(const float4*)(wp + 4));
    };
    auto sts_stage = [&](int buf) {
        char* p = sm + buf * STG;
        *(uint4*)(p + r4 * AP + s4 * 16) = rA;
        *(uint4*)(p + ABYT + r4 * AP + s4 * 16) = rB;
    };
    auto compute = [&](int buf) {
        uint32_t base = sbase + buf * STG;
#pragma unroll
        for (int kk = 0; kk < 32; kk += 16) {
            uint32_t a_h[2][4], b_h[2][4];
#pragma unroll
            for (int mt = 0; mt < 2; mt++) {
                uint32_t ad = base + (wm * 32 + mt * 16 + lrow) * AP + (kk + lk) * 2;
                ldsm_x4(ad, a_h[mt]);
            }
#pragma unroll
            for (int np = 0; np < 2; np++) {
                uint32_t bd = base + ABYT + (wn * 32 + np * 16 + lrow) * AP + (kk + lk) * 2;
                ldsm_x4(bd, b_h[np]);
            }
#pragma unroll
            for (int mt = 0; mt < 2; mt++)
#pragma unroll
                for (int nt = 0; nt < 4; nt++)
                    mma_bf16(acc[mt][nt], a_h[mt], &b_h[nt >> 1][(nt & 1) * 2]);
        }
    };

    const int S = K / 32;
    ldg_stage(0);
    sts_stage(0);
    __syncthreads();
    for (int s = 0; s < S; s++) {
        if (s + 1 < S) ldg_stage((s + 1) * 32);
        compute(s & 1);
        if (s + 1 < S) sts_stage((s + 1) & 1);
        __syncthreads();
    }

#pragma unroll
    for (int mt = 0; mt < 2; mt++) {
#pragma unroll
        for (int nt = 0; nt < 4; nt++) {
            int row0 = m0 + wm * 32 + mt * 16 + (lane >> 2);
            int col  = n0 + wn * 32 + nt * 8 + (lane & 3) * 2;
            float b0 = bias[col], b1 = bias[col + 1];
#pragma unroll
            for (int half = 0; half < 2; half++) {
                int row = row0 + half * 8;
                float v0 = acc[mt][nt][half * 2 + 0] + b0;
                float v1 = acc[mt][nt][half * 2 + 1] + b1;
                if (ACT == 1) { v0 = fmaxf(v0, 0.f); v1 = fmaxf(v1, 0.f); }
                else if (ACT == 2) {
                    v0 = 1.f / (1.f + expf(-v0));
                    v1 = 1.f / (1.f + expf(-v1));
                }
                if (OUT == 0) {
                    *reinterpret_cast<float2*>(&Cf[(size_t)row * N + col]) = make_float2(v0, v1);
                } else {
                    *reinterpret_cast<__nv_bfloat162*>(&Coh[(size_t)row * N + col]) =
                        __halves2bfloat162(__float2bfloat16(v0), __float2bfloat16(v1));
                }
            }
        }
    }
}

// ---------------- prep kernels ----------------
__global__ void im2col1_kernel(const float* __restrict__ data) {
    int idx = blockIdx.x * blockDim.x + threadIdx.x;
    if (idx >= M1 * K1P) return;
    int m = idx / K1P, kk = idx % K1P;
    float v = 0.f;
    if (kk < 81) {
        int b = m / P1, pos = m % P1;
        int y = pos / H1S, x = pos % H1S;
        int ky = kk / 9, kx = kk % 9;
        v = data[(size_t)b * 400 + (y + ky) * 20 + (x + kx)];
    }
    g_A1h[idx] = __float2bfloat16(v);
}
__global__ void permute_w1_kernel(const float* __restrict__ conv1_w) {
    int idx = blockIdx.x * blockDim.x + threadIdx.x;
    if (idx >= 256 * K1P) return;
    int o = idx / K1P, kk = idx % K1P;
    float v = (kk < 81) ? conv1_w[o * 81 + kk] : 0.f;
    g_W1h[idx] = __float2bfloat16(v);
}
__global__ void permute_w2_kernel(const float* __restrict__ prim_w) {
    __shared__ __nv_bfloat16 sm[K2];
    int o = blockIdx.x;
    int t = threadIdx.x;
    const float* src = prim_w + (size_t)o * K2;
    for (int idx = t; idx < K2; idx += 256)
        sm[idx] = __float2bfloat16(src[idx]);
    __syncthreads();
    __nv_bfloat16* dst = g_W2h + (size_t)o * K2;
    for (int idx = t; idx < K2; idx += 256) {
        int rr = idx >> 8, c = idx & 255;
        dst[idx] = sm[c * 81 + rr];
    }
}

// ---------------- capsule / routing kernels ----------------
__global__ void squash_kernel() {
    int t = blockIdx.x * blockDim.x + threadIdx.x;
    if (t >= BSZ * RTS) return;
    int b = t / RTS, r = t % RTS;
    int o = r >> 1, hi = r & 1;
    const float* up = &g_Up[(size_t)(b * 16 + hi * 8) * 256 + o];
    float u[8], sn = 0.f;
#pragma unroll
    for (int i = 0; i < 8; i++) {
        float v = up[(size_t)i * 256];
#pragma unroll
        for (int z = 1; z < ZSPL; z++) v += up[(size_t)z * USLICE + (size_t)i * 256];
        u[i] = v; sn += v * v;
    }
    float sc = sn / ((1.f + sn) * sqrtf(sn));
#pragma unroll
    for (int i = 0; i < 8; i++) g_X[(size_t)t * 8 + i] = u[i] * sc;
}
__global__ void uhat_kernel(const float* __restrict__ Wd) {
    int r = blockIdx.x;
    int b0 = blockIdx.y * 32;
    int t = threadIdx.x;       // 160: t = c*16+o
    __shared__ float Wr[1280];
    __shared__ float Xr[256];
    for (int q = t; q < 1280; q += 160) Wr[q] = Wd[(size_t)r * 1280 + q];
    for (int q = t; q < 256; q += 160) {
        int b = q >> 3, i = q & 7;
        Xr[q] = g_X[(size_t)((b0 + b) * RTS + r) * 8 + i];
    }
    __syncthreads();
    for (int b = 0; b < 32; b++) {
        float acc = 0.f;
#pragma unroll
        for (int i = 0; i < 8; i++) acc = fmaf(Wr[t * 8 + i], Xr[b * 8 + i], acc);
        g_UH[(size_t)((b0 + b) * RTS + r) * 160 + t] = __float2bfloat16(acc);
    }
}
__global__ void softmax_routes_kernel() {
    __shared__ float sm[RTS * NCP];
    __shared__ float mx[NCP], sum[NCP];
    int t = threadIdx.x; // 512
    for (int q = t; q < RTS * NCP; q += 512) sm[q] = g_BIJ[q];
    __syncthreads();
    if (t < NCP) {
        float m = -1e30f;
        for (int r = 0; r < RTS; r++) m = fmaxf(m, sm[r * NCP + t]);
        float s = 0.f;
        for (int r = 0; r < RTS; r++) s += expf(sm[r * NCP + t] - m);
        mx[t] = m; sum[t] = s;
    }
    __syncthreads();
    for (int q = t; q < RTS * NCP; q += 512) {
        int j = q % NCP;
        g_CIJ[q] = expf(sm[q] - mx[j]) / sum[j];
    }
}
template<int UNIFORM, int AGREE, int WRITEV>
__global__ __launch_bounds__(512)
void route_fused_kernel(float* __restrict__ agp) {
    extern __shared__ float smr[];               // [512*81] UH words, then cs
    float* cs = smr + 512 * 81;
    __shared__ float v_s[160];
    const int b = blockIdx.x;
    const int t = threadIdx.x;

    const uint32_t* src = reinterpret_cast<const uint32_t*>(&g_UH[(size_t)b * RTS * 160]);
    uint32_t* uw = reinterpret_cast<uint32_t*>(smr);
    for (int q = t; q < RTS * 80; q += 512) {
        int r = q / 80, ww = q - r * 80;
        uw[r * 81 + ww] = src[q];
    }
    if (!UNIFORM)
        for (int q = t; q < RTS * NCP; q += 512) cs[q] = g_CIJ[q];
    __syncthreads();

    if (t < 160) {
        int j = t >> 4;
        int wdx = t >> 1, hi = t & 1;
        float acc = 0.f;
        for (int r = 0; r < RTS; r++) {
            uint32_t u2 = uw[r * 81 + wdx];
            float2 a = __bfloat1622float2(*reinterpret_cast<__nv_bfloat162*>(&u2));
            float u = hi ? a.y : a.x;
            float c = UNIFORM ? (1.f / 512.f) : cs[r * NCP + j];
            acc = fmaf(c, u, acc);
        }
        float sq = acc * acc;
        float v = sq * acc / ((1.f + sq) * sqrtf(sq));
        v_s[t] = v;
        if (WRITEV) g_V[b * 160 + t] = v;
    }
    __syncthreads();

    if (AGREE) {
        int r = t;
        const uint32_t* row = uw + r * 81;
#pragma unroll
        for (int j = 0; j < NCP; j++) {
            float d = 0.f;
#pragma unroll
            for (int ww = 0; ww < 8; ww++) {
                uint32_t u2 = row[j * 8 + ww];
                float2 a = __bfloat1622float2(*reinterpret_cast<__nv_bfloat162*>(&u2));
                d += a.x * v_s[j * 16 + ww * 2] + a.y * v_s[j * 16 + ww * 2 + 1];
            }
            agp[(size_t)b * 5120 + j * 512 + r] = d;
        }
    }
}
__global__ void route_reduce_kernel(const float* __restrict__ agp, int first) {
    int q = blockIdx.x * 512 + threadIdx.x;   // 5120
    float s = 0.f;
    for (int b = 0; b < BSZ; b++) s += agp[(size_t)b * 5120 + q];
    int j = q >> 9, r = q & 511;
    float val = s * (1.f / 256.f);
    if (first) g_BIJ[r * NCP + j] = val;
    else       g_BIJ[r * NCP + j] += val;
}
__global__ void classes_argmax_kernel() {
    int b = threadIdx.x; // 256
    __shared__ float cl[256 * NCP];
    __shared__ float lz[NCP];
    for (int j = 0; j < NCP; j++) {
        float s = 0.f;
        for (int o = 0; o < 16; o++) {
            float v = g_V[b * 160 + j * 16 + o];
            s += v * v;
        }
        cl[b * NCP + j] = sqrtf(s);
    }
    __syncthreads();
    if (b < NCP) {
        float m = -1e30f;
        for (int q = 0; q < 256; q++) m = fmaxf(m, cl[q * NCP + b]);
        float s = 0.f;
        for (int q = 0; q < 256; q++) s += expf(cl[q * NCP + b] - m);
        lz[b] = m + logf(s);
    }
    __syncthreads();
    int best = 0;
    float bv = cl[b * NCP + 0] - lz[0];
    for (int j = 1; j < NCP; j++) {
        float v = cl[b * NCP + j] - lz[j];
        if (v > bv) { bv = v; best = j; }
    }
    g_IDX[b] = best;
}
__global__ void dec1_kernel(const float* __restrict__ w1, const float* __restrict__ b1) {
    int b = blockIdx.x;    // 256
    int k = threadIdx.x;   // 512
    __shared__ float vs[16];
    __shared__ int idx;
    if (k == 0) idx = g_IDX[b];
    __syncthreads();
    if (k < 16) vs[k] = g_V[b * 160 + idx * 16 + k];
    __syncthreads();
    float acc = b1[k];
    const float* wp = &w1[(size_t)k * 160 + idx * 16];
#pragma unroll
    for (int o = 0; o < 16; o++) acc = fmaf(vs[o], wp[o], acc);
    g_H1h[b * DEC1 + k] = __float2bfloat16(fmaxf(acc, 0.f));
}

// ---------------- launch ----------------
extern "C" void kernel_launch(void* const* d_in, const int* in_sizes, int n_in,
                              void* d_out, int out_size) {
    const float* data    = (const float*)d_in[0];
    const float* conv1_w = (const float*)d_in[1];
    const float* conv1_b = (const float*)d_in[2];
    const float* prim_w  = (const float*)d_in[3];
    const float* prim_b  = (const float*)d_in[4];
    const float* W_digit = (const float*)d_in[5];
    const float* dec_w1  = (const float*)d_in[6];
    const float* dec_b1  = (const float*)d_in[7];
    const float* dec_w2  = (const float*)d_in[8];
    const float* dec_b2  = (const float*)d_in[9];
    const float* dec_w3  = (const float*)d_in[10];
    const float* dec_b3  = (const float*)d_in[11];
    float* out = (float*)d_out;

    __nv_bfloat16 *pA1h, *pW1h, *pC1h, *pW2h, *pH1h, *pH2h;
    float *pUp;
    cudaGetSymbolAddress((void**)&pA1h, g_A1h);
    cudaGetSymbolAddress((void**)&pW1h, g_W1h);
    cudaGetSymbolAddress((void**)&pC1h, g_C1h);
    cudaGetSymbolAddress((void**)&pW2h, g_W2h);
    cudaGetSymbolAddress((void**)&pH1h, g_H1h);
    cudaGetSymbolAddress((void**)&pH2h, g_H2h);
    cudaGetSymbolAddress((void**)&pUp, g_Up);

    constexpr int SMA = 3 * 20480;                  // async 3-stage
    constexpr int SMB = 2 * 20480;                  // wf 2-stage
    constexpr int SMR = 512 * 81 * 4 + 5120 * 4;    // fused routing
    cudaFuncSetAttribute((const void*)hmma_gemm_async<0, 1, 2, 0>, cudaFuncAttributeMaxDynamicSharedMemorySize, SMA);
    cudaFuncSetAttribute((const void*)hmma_gemm_async<1, 0, 0, 1>, cudaFuncAttributeMaxDynamicSharedMemorySize, SMA);
    cudaFuncSetAttribute((const void*)hmma_gemm_wf<1, 2>, cudaFuncAttributeMaxDynamicSharedMemorySize, SMB);
    cudaFuncSetAttribute((const void*)hmma_gemm_wf<2, 0>, cudaFuncAttributeMaxDynamicSharedMemorySize, SMB);
    cudaFuncSetAttribute((const void*)route_fused_kernel<1, 1, 0>, cudaFuncAttributeMaxDynamicSharedMemorySize, SMR);
    cudaFuncSetAttribute((const void*)route_fused_kernel<0, 1, 0>, cudaFuncAttributeMaxDynamicSharedMemorySize, SMR);
    cudaFuncSetAttribute((const void*)route_fused_kernel<0, 0, 1>, cudaFuncAttributeMaxDynamicSharedMemorySize, SMR);

    // weight preps
    permute_w1_kernel<<<(256 * K1P + 255) / 256, 256>>>(conv1_w);
    permute_w2_kernel<<<256, 256>>>(prim_w);

    // 1) conv1: async bf16 HMMA, relu, bf16 out
    im2col1_kernel<<<(M1 * K1P + 255) / 256, 256>>>(data);
    hmma_gemm_async<0, 1, 2, 0><<<dim3(M1 / 128, 256 / 128), 512, SMA>>>(
        pA1h, pW1h, conv1_b, nullptr, pC1h, 256, K1P);

    // 2) primary caps: implicit im2col async, split-K=8 partials
    hmma_gemm_async<1, 0, 0, 1><<<dim3(M2 / 128, 256 / 128, ZSPL), 512, SMA>>>(
        pC1h, pW2h, prim_b, pUp, nullptr, 256, K2);

    // 3) squash (fused split-K reduce) + u_hat (bf16 out)
    squash_kernel<<<(BSZ * RTS + 255) / 256, 256>>>();
    uhat_kernel<<<dim3(RTS, 8), 160>>>(W_digit);

    // 4) fused dynamic routing
    route_fused_kernel<1, 1, 0><<<BSZ, 512, SMR>>>(pUp);
    route_reduce_kernel<<<10, 512>>>(pUp, 1);
    softmax_routes_kernel<<<1, 512>>>();
    route_fused_kernel<0, 1, 0><<<BSZ, 512, SMR>>>(pUp);
    route_reduce_kernel<<<10, 512>>>(pUp, 0);
    softmax_routes_kernel<<<1, 512>>>();
    route_fused_kernel<0, 0, 1><<<BSZ, 512, SMR>>>(pUp);

    // 5) classes / mask / decoder
    classes_argmax_kernel<<<1, 256>>>();
    dec1_kernel<<<BSZ, DEC1>>>(dec_w1, dec_b1);
    hmma_gemm_wf<1, 2><<<dim3(BSZ / 128, DEC2 / 128), 512, SMB>>>(
        pH1h, dec_w2, dec_b2, nullptr, pH2h, DEC2, DEC1);
    hmma_gemm_wf<2, 0><<<dim3(BSZ / 128, RECS / 128), 512, SMB>>>(
        pH2h, dec_w3, dec_b3, out, nullptr, RECS, DEC2);
}

// round 11
// speedup vs baseline: 1.3230x; 1.3230x over previous
#include <cuda_runtime.h>
#include <cuda_bf16.h>
#include <math.h>
#include <stdint.h>

// ---------------- problem constants ----------------
#define BSZ   256
#define H1S   12
#define P1    144
#define RTS   512
#define NCP   10
#define K1P   96          // conv1 K padded 81 -> 96 (3 stages of 32)
#define K2    20736
#define M1    (BSZ*P1)    // 36864
#define M2    4096
#define RECS  102400
#define DEC1  512
#define DEC2  1024
#define ZSPL  4
#define USLICE (M2 * 256)

// ---------------- scratch ----------------
__device__ __nv_bfloat16 g_A1h[M1 * K1P];
__device__ __nv_bfloat16 g_W1h[256 * K1P];
__device__ __nv_bfloat16 g_C1h[M1 * 256];
__device__ __nv_bfloat16 g_W2h[256 * K2];
__device__ float         g_Up[ZSPL * USLICE];   // split-K partials; reused as agreement partials
__device__ __nv_bfloat16 g_H1h[BSZ * DEC1];
__device__ __nv_bfloat16 g_H2h[BSZ * DEC2];
__device__ float g_X [BSZ * RTS * 8];
__device__ __nv_bfloat16 g_UH[(size_t)BSZ * RTS * 160];
__device__ float g_BIJ[RTS * NCP];
__device__ float g_V [BSZ * 160];
__device__ int   g_IDX[BSZ];

// ---------------- helpers ----------------
__device__ __forceinline__ uint32_t smem_u32(const void* p) {
    uint32_t a;
    asm("{ .reg .u64 t; cvta.to.shared.u64 t, %1; cvt.u32.u64 %0, t; }" : "=r"(a) : "l"(p));
    return a;
}
__device__ __forceinline__ void ldsm_x4(uint32_t addr, uint32_t* r) {
    asm volatile("ldmatrix.sync.aligned.m8n8.x4.shared.b16 {%0,%1,%2,%3}, [%4];"
        : "=r"(r[0]), "=r"(r[1]), "=r"(r[2]), "=r"(r[3]) : "r"(addr));
}
__device__ __forceinline__ void mma_bf16(float* c, const uint32_t* a, const uint32_t* b) {
    asm volatile(
        "mma.sync.aligned.m16n8k16.row.col.f32.bf16.bf16.f32 "
        "{%0,%1,%2,%3}, {%4,%5,%6,%7}, {%8,%9}, {%0,%1,%2,%3};"
        : "+f"(c[0]), "+f"(c[1]), "+f"(c[2]), "+f"(c[3])
        : "r"(a[0]), "r"(a[1]), "r"(a[2]), "r"(a[3]), "r"(b[0]), "r"(b[1]));
}
__device__ __forceinline__ uint4 pack8bf16(float4 f0, float4 f1) {
    __nv_bfloat162 p0 = __halves2bfloat162(__float2bfloat16(f0.x), __float2bfloat16(f0.y));
    __nv_bfloat162 p1 = __halves2bfloat162(__float2bfloat16(f0.z), __float2bfloat16(f0.w));
    __nv_bfloat162 p2 = __halves2bfloat162(__float2bfloat16(f1.x), __float2bfloat16(f1.y));
    __nv_bfloat162 p3 = __halves2bfloat162(__float2bfloat16(f1.z), __float2bfloat16(f1.w));
    uint4 r;
    r.x = *reinterpret_cast<uint32_t*>(&p0);
    r.y = *reinterpret_cast<uint32_t*>(&p1);
    r.z = *reinterpret_cast<uint32_t*>(&p2);
    r.w = *reinterpret_cast<uint32_t*>(&p3);
    return r;
}
__device__ __forceinline__ void cp16(uint32_t d, const void* s) {
    asm volatile("cp.async.cg.shared.global [%0], [%1], 16;" :: "r"(d), "l"(s));
}
__device__ __forceinline__ void cp_commit() { asm volatile("cp.async.commit_group;"); }
template<int NW> __device__ __forceinline__ void cp_wait() {
    asm volatile("cp.async.wait_group %0;" :: "n"(NW));
}

// ============ async HMMA bf16 NT GEMM, BM=128 BN=128 BK=32, 256 thr (8 warps 4x2) ============
template<int MODE, int ACT, int OUT, int SPLITK, int STAGES>
__global__ __launch_bounds__(256)
void hmma_gemm_async(const __nv_bfloat16* __restrict__ Ah,
                     const __nv_bfloat16* __restrict__ Wh,
                     const float* __restrict__ bias,
                     float* __restrict__ Cf,
                     __nv_bfloat16* __restrict__ Coh,
                     int N, int K)
{
    extern __shared__ char sm[];
    constexpr int AP   = 80;
    constexpr int ABYT = 128 * AP;
    constexpr int STG  = 2 * ABYT;   // 20480

    const int t = threadIdx.x;
    const int m0 = blockIdx.x * 128;
    const int n0 = blockIdx.y * 128;
    const uint32_t sbase = smem_u32(sm);

    int r4[2], s4[2], mbase[2];
#pragma unroll
    for (int i = 0; i < 2; i++) {
        int idx = t + i * 256;
        r4[i] = idx >> 2; s4[i] = idx & 3;
        if (MODE == 1) {
            int m = m0 + r4[i]; int b = m >> 4, p = m & 15;
            mbase[i] = b * 144 + (p >> 2) * 12 + (p & 3);
        }
    }

    const int w = t >> 5, lane = t & 31;
    const int wm = w >> 1, wn = w & 1;          // 4x2 warps, 32x64 tile
    const int lrow = (lane & 7) + ((lane >> 3) & 1) * 8;
    const int lk   = ((lane >> 4) & 1) * 8;

    float acc[2][8][4];
#pragma unroll
    for (int mt = 0; mt < 2; mt++)
#pragma unroll
        for (int nt = 0; nt < 8; nt++)
#pragma unroll
            for (int q = 0; q < 4; q++) acc[mt][nt][q] = 0.f;

    auto issue = [&](int s, int k0) {
        uint32_t sb = sbase + (s % STAGES) * STG;
#pragma unroll
        for (int i = 0; i < 2; i++) {
            size_t aoff;
            if (MODE == 0) {
                aoff = (size_t)(m0 + r4[i]) * K + k0 + s4[i] * 8;
            } else {
                int rr = k0 >> 8;
                int rowg = mbase[i] + (rr / 9) * 12 + (rr % 9);
                aoff = (size_t)rowg * 256 + (k0 & 255) + s4[i] * 8;
            }
            cp16(sb + r4[i] * AP + s4[i] * 16, Ah + aoff);
            cp16(sb + ABYT + r4[i] * AP + s4[i] * 16,
                 Wh + (size_t)(n0 + r4[i]) * K + k0 + s4[i] * 8);
        }
    };
    auto compute = [&](int buf) {
        uint32_t base = sbase + buf * STG;
#pragma unroll
        for (int kk = 0; kk < 32; kk += 16) {
            uint32_t a_h[2][4], b_h[4][4];
#pragma unroll
            for (int mt = 0; mt < 2; mt++) {
                uint32_t ad = base + (wm * 32 + mt * 16 + lrow) * AP + (kk + lk) * 2;
                ldsm_x4(ad, a_h[mt]);
            }
#pragma unroll
            for (int np = 0; np < 4; np++) {
                uint32_t bd = base + ABYT + (wn * 64 + np * 16 + lrow) * AP + (kk + lk) * 2;
                ldsm_x4(bd, b_h[np]);
            }
#pragma unroll
            for (int mt = 0; mt < 2; mt++)
#pragma unroll
                for (int nt = 0; nt < 8; nt++)
                    mma_bf16(acc[mt][nt], a_h[mt], &b_h[nt >> 1][(nt & 1) * 2]);
        }
    };

    const int S = SPLITK ? (K / 32 / ZSPL) : (K / 32);
    const int kbase = SPLITK ? blockIdx.z * (K / ZSPL) : 0;
#pragma unroll
    for (int p = 0; p < STAGES - 1; p++) {
        if (p < S) issue(p, kbase + p * 32);
        cp_commit();
    }
    for (int s = 0; s < S; s++) {
        cp_wait<STAGES - 2>();
        __syncthreads();
        if (s + STAGES - 1 < S) issue(s + STAGES - 1, kbase + (s + STAGES - 1) * 32);
        cp_commit();
        compute(s % STAGES);
    }

    // ---- epilogue ----
    const size_t zoff = SPLITK ? (size_t)blockIdx.z * (size_t)(gridDim.x * 128) * N : 0;
#pragma unroll
    for (int mt = 0; mt < 2; mt++) {
#pragma unroll
        for (int nt = 0; nt < 8; nt++) {
            int row0 = m0 + wm * 32 + mt * 16 + (lane >> 2);
            int col  = n0 + wn * 64 + nt * 8 + (lane & 3) * 2;
            float b0, b1;
            if (SPLITK && blockIdx.z != 0) { b0 = 0.f; b1 = 0.f; }
            else { b0 = bias[col]; b1 = bias[col + 1]; }
#pragma unroll
            for (int half = 0; half < 2; half++) {
                int row = row0 + half * 8;
                float v0 = acc[mt][nt][half * 2 + 0] + b0;
                float v1 = acc[mt][nt][half * 2 + 1] + b1;
                if (ACT == 1) { v0 = fmaxf(v0, 0.f); v1 = fmaxf(v1, 0.f); }
                if (OUT == 0) {
                    *reinterpret_cast<float2*>(&Cf[zoff + (size_t)row * N + col]) = make_float2(v0, v1);
                } else {
                    *reinterpret_cast<__nv_bfloat162*>(&Coh[(size_t)row * N + col]) =
                        __halves2bfloat162(__float2bfloat16(v0), __float2bfloat16(v1));
                }
            }
        }
    }
}

// ============ 2-stage HMMA GEMM, fp32 W converted in loader, 256 thr ============
template<int ACT, int OUT>
__global__ __launch_bounds__(256)
void hmma_gemm_wf(const __nv_bfloat16* __restrict__ Ah,
                  const float* __restrict__ Wf,
                  const float* __restrict__ bias,
                  float* __restrict__ Cf,
                  __nv_bfloat16* __restrict__ Coh,
                  int N, int K)
{
    extern __shared__ char sm[];
    constexpr int AP   = 80;
    constexpr int ABYT = 128 * AP;
    constexpr int STG  = 2 * ABYT;

    const int t = threadIdx.x;
    const int m0 = blockIdx.x * 128;
    const int n0 = blockIdx.y * 128;
    const uint32_t sbase = smem_u32(sm);

    int r4[2], s4[2];
#pragma unroll
    for (int i = 0; i < 2; i++) {
        int idx = t + i * 256;
        r4[i] = idx >> 2; s4[i] = idx & 3;
    }
    const int w = t >> 5, lane = t & 31;
    const int wm = w >> 1, wn = w & 1;
    const int lrow = (lane & 7) + ((lane >> 3) & 1) * 8;
    const int lk   = ((lane >> 4) & 1) * 8;

    float acc[2][8][4];
#pragma unroll
    for (int mt = 0; mt < 2; mt++)
#pragma unroll
        for (int nt = 0; nt < 8; nt++)
#pragma unroll
            for (int q = 0; q < 4; q++) acc[mt][nt][q] = 0.f;

    uint4 rA[2], rB[2];
    auto ldg_stage = [&](int k0) {
#pragma unroll
        for (int i = 0; i < 2; i++) {
            rA[i] = *(const uint4*)(Ah + (size_t)(m0 + r4[i]) * K + k0 + s4[i] * 8);
            const float* wp = Wf + (size_t)(n0 + r4[i]) * K + k0 + s4[i] * 8;
            rB[i] = pack8bf16(*(const float4*)wp, *(const float4*)(wp + 4));
        }
    };
    auto sts_stage = [&](int buf) {
        char* p = sm + buf * STG;
#pragma unroll
        for (int i = 0; i < 2; i++) {
            *(uint4*)(p + r4[i] * AP + s4[i] * 16) = rA[i];
            *(uint4*)(p + ABYT + r4[i] * AP + s4[i] * 16) = rB[i];
        }
    };
    auto compute = [&](int buf) {
        uint32_t base = sbase + buf * STG;
#pragma unroll
        for (int kk = 0; kk < 32; kk += 16) {
            uint32_t a_h[2][4], b_h[4][4];
#pragma unroll
            for (int mt = 0; mt < 2; mt++) {
                uint32_t ad = base + (wm * 32 + mt * 16 + lrow) * AP + (kk + lk) * 2;
                ldsm_x4(ad, a_h[mt]);
            }
#pragma unroll
            for (int np = 0; np < 4; np++) {
                uint32_t bd = base + ABYT + (wn * 64 + np * 16 + lrow) * AP + (kk + lk) * 2;
                ldsm_x4(bd, b_h[np]);
            }
#pragma unroll
            for (int mt = 0; mt < 2; mt++)
#pragma unroll
                for (int nt = 0; nt < 8; nt++)
                    mma_bf16(acc[mt][nt], a_h[mt], &b_h[nt >> 1][(nt & 1) * 2]);
        }
    };

    const int S = K / 32;
    ldg_stage(0);
    sts_stage(0);
    __syncthreads();
    for (int s = 0; s < S; s++) {
        if (s + 1 < S) ldg_stage((s + 1) * 32);
        compute(s & 1);
        if (s + 1 < S) sts_stage((s + 1) & 1);
        __syncthreads();
    }

#pragma unroll
    for (int mt = 0; mt < 2; mt++) {
#pragma unroll
        for (int nt = 0; nt < 8; nt++) {
            int row0 = m0 + wm * 32 + mt * 16 + (lane >> 2);
            int col  = n0 + wn * 64 + nt * 8 + (lane & 3) * 2;
            float b0 = bias[col], b1 = bias[col + 1];
#pragma unroll
            for (int half = 0; half < 2; half++) {
                int row = row0 + half * 8;
                float v0 = acc[mt][nt][half * 2 + 0] + b0;
                float v1 = acc[mt][nt][half * 2 + 1] + b1;
                if (ACT == 1) { v0 = fmaxf(v0, 0.f); v1 = fmaxf(v1, 0.f); }
                else if (ACT == 2) {
                    v0 = 1.f / (1.f + expf(-v0));
                    v1 = 1.f / (1.f + expf(-v1));
                }
                if (OUT == 0) {
                    *reinterpret_cast<float2*>(&Cf[(size_t)row * N + col]) = make_float2(v0, v1);
                } else {
                    *reinterpret_cast<__nv_bfloat162*>(&Coh[(size_t)row * N + col]) =
                        __halves2bfloat162(__float2bfloat16(v0), __float2bfloat16(v1));
                }
            }
        }
    }
}

// ---------------- prep kernels ----------------
__global__ void im2col1_kernel(const float* __restrict__ data) {
    int idx = blockIdx.x * blockDim.x + threadIdx.x;
    if (idx >= M1 * K1P) return;
    int m = idx / K1P, kk = idx % K1P;
    float v = 0.f;
    if (kk < 81) {
        int b = m / P1, pos = m % P1;
        int y = pos / H1S, x = pos % H1S;
        int ky = kk / 9, kx = kk % 9;
        v = data[(size_t)b * 400 + (y + ky) * 20 + (x + kx)];
    }
    g_A1h[idx] = __float2bfloat16(v);
}
__global__ void permute_w1_kernel(const float* __restrict__ conv1_w) {
    int idx = blockIdx.x * blockDim.x + threadIdx.x;
    if (idx >= 256 * K1P) return;
    int o = idx / K1P, kk = idx % K1P;
    float v = (kk < 81) ? conv1_w[o * 81 + kk] : 0.f;
    g_W1h[idx] = __float2bfloat16(v);
}
__global__ void permute_w2_kernel(const float* __restrict__ prim_w) {
    __shared__ __nv_bfloat16 sm[K2];
    int o = blockIdx.x;
    int t = threadIdx.x;
    const float* src = prim_w + (size_t)o * K2;
    for (int idx = t; idx < K2; idx += 256)
        sm[idx] = __float2bfloat16(src[idx]);
    __syncthreads();
    __nv_bfloat16* dst = g_W2h + (size_t)o * K2;
    for (int idx = t; idx < K2; idx += 256) {
        int rr = idx >> 8, c = idx & 255;
        dst[idx] = sm[c * 81 + rr];
    }
}

// ---------------- capsule / routing kernels ----------------
__global__ void squash_kernel() {
    int t = blockIdx.x * blockDim.x + threadIdx.x;
    if (t >= BSZ * RTS) return;
    int b = t / RTS, r = t % RTS;
    int o = r >> 1, hi = r & 1;
    const float* up = &g_Up[(size_t)(b * 16 + hi * 8) * 256 + o];
    float u[8], sn = 0.f;
#pragma unroll
    for (int i = 0; i < 8; i++) {
        float v = up[(size_t)i * 256];
#pragma unroll
        for (int z = 1; z < ZSPL; z++) v += up[(size_t)z * USLICE + (size_t)i * 256];
        u[i] = v; sn += v * v;
    }
    float sc = sn / ((1.f + sn) * sqrtf(sn));
#pragma unroll
    for (int i = 0; i < 8; i++) g_X[(size_t)t * 8 + i] = u[i] * sc;
}
__global__ void uhat_kernel(const float* __restrict__ Wd) {
    int r = blockIdx.x;
    int b0 = blockIdx.y * 32;
    int t = threadIdx.x;       // 160: t = c*16+o
    __shared__ float Wr[1280];
    __shared__ float Xr[256];
    for (int q = t; q < 1280; q += 160) Wr[q] = Wd[(size_t)r * 1280 + q];
    for (int q = t; q < 256; q += 160) {
        int b = q >> 3, i = q & 7;
        Xr[q] = g_X[(size_t)((b0 + b) * RTS + r) * 8 + i];
    }
    __syncthreads();
    for (int b = 0; b < 32; b++) {
        float acc = 0.f;
#pragma unroll
        for (int i = 0; i < 8; i++) acc = fmaf(Wr[t * 8 + i], Xr[b * 8 + i], acc);
        g_UH[(size_t)((b0 + b) * RTS + r) * 160 + t] = __float2bfloat16(acc);
    }
}

// ---- fused routing: one block per b; u_hat[b] smem-resident; softmax computed in-block ----
template<int UNIFORM, int AGREE, int WRITEV>
__global__ __launch_bounds__(512)
void route_fused_kernel(float* __restrict__ agp) {
    extern __shared__ float smr[];               // [512*81] UH words, then cs[5120]
    float* cs = smr + 512 * 81;
    __shared__ float v_s[160];
    __shared__ float s_mx[NCP], s_sum[NCP];
    const int b = blockIdx.x;
    const int t = threadIdx.x;
    const int w = t >> 5, lane = t & 31;

    const uint32_t* src = reinterpret_cast<const uint32_t*>(&g_UH[(size_t)b * RTS * 160]);
    uint32_t* uw = reinterpret_cast<uint32_t*>(smr);
    for (int q = t; q < RTS * 80; q += 512) {
        int r = q / 80, ww = q - r * 80;
        uw[r * 81 + ww] = src[q];
    }
    if (!UNIFORM) {
        for (int q = t; q < RTS * NCP; q += 512) cs[q] = g_BIJ[q];
    }
    __syncthreads();

    if (!UNIFORM) {
        // softmax over routes for each class j (warp j handles class j)
        if (w < NCP) {
            float m = -1e30f;
            for (int r = lane; r < RTS; r += 32) m = fmaxf(m, cs[r * NCP + w]);
#pragma unroll
            for (int o = 16; o; o >>= 1) m = fmaxf(m, __shfl_xor_sync(0xFFFFFFFFu, m, o));
            float ssum = 0.f;
            for (int r = lane; r < RTS; r += 32) ssum += expf(cs[r * NCP + w] - m);
#pragma unroll
            for (int o = 16; o; o >>= 1) ssum += __shfl_xor_sync(0xFFFFFFFFu, ssum, o);
            if (lane == 0) { s_mx[w] = m; s_sum[w] = ssum; }
        }
        __syncthreads();
        for (int q = t; q < RTS * NCP; q += 512) {
            int j = q % NCP;
            cs[q] = expf(cs[q] - s_mx[j]) / s_sum[j];
        }
        __syncthreads();
    }

    if (t < 160) {
        int j = t >> 4;
        int wdx = t >> 1, hi = t & 1;
        float acc = 0.f;
        for (int r = 0; r < RTS; r++) {
            uint32_t u2 = uw[r * 81 + wdx];
            float2 a = __bfloat1622float2(*reinterpret_cast<__nv_bfloat162*>(&u2));
            float u = hi ? a.y : a.x;
            float c = UNIFORM ? (1.f / 512.f) : cs[r * NCP + j];
            acc = fmaf(c, u, acc);
        }
        float sq = acc * acc;
        float v = sq * acc / ((1.f + sq) * sqrtf(sq));
        v_s[t] = v;
        if (WRITEV) g_V[b * 160 + t] = v;
    }
    __syncthreads();

    if (AGREE) {
        int r = t;
        const uint32_t* row = uw + r * 81;
#pragma unroll
        for (int j = 0; j < NCP; j++) {
            float d = 0.f;
#pragma unroll
            for (int ww = 0; ww < 8; ww++) {
                uint32_t u2 = row[j * 8 + ww];
                float2 a = __bfloat1622float2(*reinterpret_cast<__nv_bfloat162*>(&u2));
                d += a.x * v_s[j * 16 + ww * 2] + a.y * v_s[j * 16 + ww * 2 + 1];
            }
            agp[(size_t)b * 5120 + j * 512 + r] = d;
        }
    }
}
__global__ void route_reduce_kernel(const float* __restrict__ agp, int first) {
    int q = blockIdx.x * 512 + threadIdx.x;   // 5120
    float s = 0.f;
    for (int b = 0; b < BSZ; b++) s += agp[(size_t)b * 5120 + q];
    int j = q >> 9, r = q & 511;
    float val = s * (1.f / 256.f);
    if (first) g_BIJ[r * NCP + j] = val;
    else       g_BIJ[r * NCP + j] += val;
}
__global__ void classes_argmax_kernel() {
    int b = threadIdx.x; // 256
    __shared__ float cl[256 * NCP];
    __shared__ float lz[NCP];
    for (int j = 0; j < NCP; j++) {
        float s = 0.f;
        for (int o = 0; o < 16; o++) {
            float v = g_V[b * 160 + j * 16 + o];
            s += v * v;
        }
        cl[b * NCP + j] = sqrtf(s);
    }
    __syncthreads();
    if (b < NCP) {
        float m = -1e30f;
        for (int q = 0; q < 256; q++) m = fmaxf(m, cl[q * NCP + b]);
        float s = 0.f;
        for (int q = 0; q < 256; q++) s += expf(cl[q * NCP + b] - m);
        lz[b] = m + logf(s);
    }
    __syncthreads();
    int best = 0;
    float bv = cl[b * NCP + 0] - lz[0];
    for (int j = 1; j < NCP; j++) {
        float v = cl[b * NCP + j] - lz[j];
        if (v > bv) { bv = v; best = j; }
    }
    g_IDX[b] = best;
}
__global__ void dec1_kernel(const float* __restrict__ w1, const float* __restrict__ b1) {
    int b = blockIdx.x;    // 256
    int k = threadIdx.x;   // 512
    __shared__ float vs[16];
    __shared__ int idx;
    if (k == 0) idx = g_IDX[b];
    __syncthreads();
    if (k < 16) vs[k] = g_V[b * 160 + idx * 16 + k];
    __syncthreads();
    float acc = b1[k];
    const float* wp = &w1[(size_t)k * 160 + idx * 16];
#pragma unroll
    for (int o = 0; o < 16; o++) acc = fmaf(vs[o], wp[o], acc);
    g_H1h[b * DEC1 + k] = __float2bfloat16(fmaxf(acc, 0.f));
}

// ---------------- launch ----------------
extern "C" void kernel_launch(void* const* d_in, const int* in_sizes, int n_in,
                              void* d_out, int out_size) {
    const float* data    = (const float*)d_in[0];
    const float* conv1_w = (const float*)d_in[1];
    const float* conv1_b = (const float*)d_in[2];
    const float* prim_w  = (const float*)d_in[3];
    const float* prim_b  = (const float*)d_in[4];
    const float* W_digit = (const float*)d_in[5];
    const float* dec_w1  = (const float*)d_in[6];
    const float* dec_b1  = (const float*)d_in[7];
    const float* dec_w2  = (const float*)d_in[8];
    const float* dec_b2  = (const float*)d_in[9];
    const float* dec_w3  = (const float*)d_in[10];
    const float* dec_b3  = (const float*)d_in[11];
    float* out = (float*)d_out;

    __nv_bfloat16 *pA1h, *pW1h, *pC1h, *pW2h, *pH1h, *pH2h;
    float *pUp;
    cudaGetSymbolAddress((void**)&pA1h, g_A1h);
    cudaGetSymbolAddress((void**)&pW1h, g_W1h);
    cudaGetSymbolAddress((void**)&pC1h, g_C1h);
    cudaGetSymbolAddress((void**)&pW2h, g_W2h);
    cudaGetSymbolAddress((void**)&pH1h, g_H1h);
    cudaGetSymbolAddress((void**)&pH2h, g_H2h);
    cudaGetSymbolAddress((void**)&pUp, g_Up);

    constexpr int SMA3 = 3 * 20480;                 // conv1: 3-stage
    constexpr int SMA4 = 4 * 20480;                 // prim: 4-stage
    constexpr int SMB  = 2 * 20480;                 // wf 2-stage
    constexpr int SMR  = 512 * 81 * 4 + 5120 * 4;   // fused routing
    cudaFuncSetAttribute((const void*)hmma_gemm_async<0, 1, 2, 0, 3>, cudaFuncAttributeMaxDynamicSharedMemorySize, SMA3);
    cudaFuncSetAttribute((const void*)hmma_gemm_async<1, 0, 0, 1, 4>, cudaFuncAttributeMaxDynamicSharedMemorySize, SMA4);
    cudaFuncSetAttribute((const void*)hmma_gemm_wf<1, 2>, cudaFuncAttributeMaxDynamicSharedMemorySize, SMB);
    cudaFuncSetAttribute((const void*)hmma_gemm_wf<2, 0>, cudaFuncAttributeMaxDynamicSharedMemorySize, SMB);
    cudaFuncSetAttribute((const void*)route_fused_kernel<1, 1, 0>, cudaFuncAttributeMaxDynamicSharedMemorySize, SMR);
    cudaFuncSetAttribute((const void*)route_fused_kernel<0, 1, 0>, cudaFuncAttributeMaxDynamicSharedMemorySize, SMR);
    cudaFuncSetAttribute((const void*)route_fused_kernel<0, 0, 1>, cudaFuncAttributeMaxDynamicSharedMemorySize, SMR);

    // weight preps
    permute_w1_kernel<<<(256 * K1P + 255) / 256, 256>>>(conv1_w);
    permute_w2_kernel<<<256, 256>>>(prim_w);

    // 1) conv1: async bf16 HMMA (K=96, 3 stages), relu, bf16 out
    im2col1_kernel<<<(M1 * K1P + 255) / 256, 256>>>(data);
    hmma_gemm_async<0, 1, 2, 0, 3><<<dim3(M1 / 128, 256 / 128), 256, SMA3>>>(
        pA1h, pW1h, conv1_b, nullptr, pC1h, 256, K1P);

    // 2) primary caps: implicit im2col async (4 stages), split-K=4 partials
    hmma_gemm_async<1, 0, 0, 1, 4><<<dim3(M2 / 128, 256 / 128, ZSPL), 256, SMA4>>>(
        pC1h, pW2h, prim_b, pUp, nullptr, 256, K2);

    // 3) squash (fused split-K reduce) + u_hat (bf16 out)
    squash_kernel<<<(BSZ * RTS + 255) / 256, 256>>>();
    uhat_kernel<<<dim3(RTS, 8), 160>>>(W_digit);

    // 4) fused dynamic routing (softmax folded into route_fused)
    route_fused_kernel<1, 1, 0><<<BSZ, 512, SMR>>>(pUp);
    route_reduce_kernel<<<10, 512>>>(pUp, 1);
    route_fused_kernel<0, 1, 0><<<BSZ, 512, SMR>>>(pUp);
    route_reduce_kernel<<<10, 512>>>(pUp, 0);
    route_fused_kernel<0, 0, 1><<<BSZ, 512, SMR>>>(pUp);

    // 5) classes / mask / decoder
    classes_argmax_kernel<<<1, 256>>>();
    dec1_kernel<<<BSZ, DEC1>>>(dec_w1, dec_b1);
    hmma_gemm_wf<1, 2><<<dim3(BSZ / 128, DEC2 / 128), 256, SMB>>>(
        pH1h, dec_w2, dec_b2, nullptr, pH2h, DEC2, DEC1);
    hmma_gemm_wf<2, 0><<<dim3(BSZ / 128, RECS / 128), 256, SMB>>>(
        pH2h, dec_w3, dec_b3, out, nullptr, RECS, DEC2);
}